// round 4
// baseline (speedup 1.0000x reference)
#include <cuda_runtime.h>
#include <cstdint>

#define E_NUM   500000
#define H_DIM   256
#define PAIRS   (E_NUM / 2)      // 250000
#define BN_EPS  1e-5f
#define GRID    444              // 148 SMs x 3 co-resident blocks
#define NWORK   443              // stats blocks 1..443
#define PER1    565              // ceil(250000/443)
#define PER2    564              // ceil(250000/444)

typedef unsigned long long u64;

// -------- device scratch (static, no allocation) --------
__device__ float g_sum[H_DIM];                     // zero-init
__device__ float g_sumsq[H_DIM];
__device__ __align__(16) u64 g_nc2[PAIRS * 8];     // packed nc pairs, 16 MB
__device__ float g_Craw[H_DIM * 8];                // W2@Wv@Wo@Wp
__device__ float g_biaspart[8];                    // b2@P2 + bv@P1 + bo@Wp + bp
__device__ unsigned g_arrive = 0;
__device__ volatile unsigned g_release = 0;
__device__ unsigned g_finish = 0;

// -------- f32x2 helpers --------
__device__ __forceinline__ u64 pack2(float lo, float hi) {
    u64 r;
    asm("mov.b64 %0, {%1, %2};" : "=l"(r)
        : "r"(__float_as_uint(lo)), "r"(__float_as_uint(hi)));
    return r;
}
__device__ __forceinline__ void unpack2(u64 v, float &lo, float &hi) {
    unsigned int a, b;
    asm("mov.b64 {%0, %1}, %2;" : "=r"(a), "=r"(b) : "l"(v));
    lo = __uint_as_float(a); hi = __uint_as_float(b);
}
__device__ __forceinline__ u64 fma2(u64 a, u64 b, u64 c) {
    u64 d;
    asm("fma.rn.f32x2 %0, %1, %2, %3;" : "=l"(d) : "l"(a), "l"(b), "l"(c));
    return d;
}
__device__ __forceinline__ u64 mul2(u64 a, u64 b) {
    u64 d;
    asm("mul.rn.f32x2 %0, %1, %2;" : "=l"(d) : "l"(a), "l"(b));
    return d;
}
__device__ __forceinline__ u64 add2(u64 a, u64 b) {
    u64 d;
    asm("add.rn.f32x2 %0, %1, %2;" : "=l"(d) : "l"(a), "l"(b));
    return d;
}
__device__ __forceinline__ u64 relu2(u64 h) {
    float lo, hi; unpack2(h, lo, hi);
    return pack2(fmaxf(lo, 0.f), fmaxf(hi, 0.f));
}
__device__ __forceinline__ float wred(float v) {
    v += __shfl_down_sync(0xffffffffu, v, 16);
    v += __shfl_down_sync(0xffffffffu, v, 8);
    v += __shfl_down_sync(0xffffffffu, v, 4);
    v += __shfl_down_sync(0xffffffffu, v, 2);
    v += __shfl_down_sync(0xffffffffu, v, 1);
    return v;
}

__global__ void __launch_bounds__(256, 3)
fused(const float* __restrict__ ea, const float* __restrict__ nf,
      const int*   __restrict__ eidx,
      const float* __restrict__ W1, const float* __restrict__ b1,
      const float* __restrict__ gamma, const float* __restrict__ beta,
      const float* __restrict__ W2, const float* __restrict__ b2,
      const float* __restrict__ Wv, const float* __restrict__ bv,
      const float* __restrict__ Wo, const float* __restrict__ bo,
      const float* __restrict__ Wp, const float* __restrict__ bp,
      float* __restrict__ out)
{
    // union region: phase1 nc tile (4 groups x 256 ulonglong2 = 16KB)
    //             / block0 chain bufs (2 x 2304 floats = 18432B)
    //             / phase2 ms table (2048 u64 = 16KB)
    __shared__ __align__(16) unsigned char s_buf[18432];
    __shared__ __align__(16) u64 w1s[H_DIM * 8];   // W1^T duplicated
    __shared__ u64 b1s[H_DIM];
    __shared__ u64 dh_s[8];
    __shared__ float a_s[H_DIM], c_s[H_DIM];

    const int t = threadIdx.x;
    const int b = blockIdx.x;
    const int lane = t & 31, warp = t >> 5;

    // duplicated W1^T / b1 tables (own-slot writes)
    #pragma unroll
    for (int d = 0; d < 8; d++) {
        float v = W1[d * H_DIM + t];
        w1s[t * 8 + d] = pack2(v, v);
    }
    { float bb = b1[t]; b1s[t] = pack2(bb, bb); }

    if (b == 0) {
        // ============ weight chain (overlaps the stats pass) ============
        float* bufA = (float*)s_buf;      // 256 rows x 9 floats (padded)
        float* bufB = bufA + 2304;
        for (int i = t; i < H_DIM * 8; i += 256)
            bufA[(i >> 3) * 9 + (i & 7)] = Wp[i];
        __syncthreads();
        float biask = 0.f;
        for (int j = lane; j < H_DIM; j += 32) biask += bo[j] * bufA[j * 9 + warp];
        // P1 = Wo @ Wp
        for (int jj = warp; jj < H_DIM; jj += 8) {
            float a0=0,a1=0,a2=0,a3=0,a4=0,a5=0,a6=0,a7=0;
            #pragma unroll
            for (int qb = 0; qb < 8; qb++) {
                int q = qb * 32 + lane;
                float av = Wo[jj * H_DIM + q];
                const float* ir = bufA + q * 9;
                a0 += av*ir[0]; a1 += av*ir[1]; a2 += av*ir[2]; a3 += av*ir[3];
                a4 += av*ir[4]; a5 += av*ir[5]; a6 += av*ir[6]; a7 += av*ir[7];
            }
            a0=wred(a0); a1=wred(a1); a2=wred(a2); a3=wred(a3);
            a4=wred(a4); a5=wred(a5); a6=wred(a6); a7=wred(a7);
            if (lane == 0) {
                float* orow = bufB + jj * 9;
                orow[0]=a0; orow[1]=a1; orow[2]=a2; orow[3]=a3;
                orow[4]=a4; orow[5]=a5; orow[6]=a6; orow[7]=a7;
            }
        }
        __syncthreads();
        for (int j = lane; j < H_DIM; j += 32) biask += bv[j] * bufB[j * 9 + warp];
        // P2 = Wv @ P1
        for (int jj = warp; jj < H_DIM; jj += 8) {
            float a0=0,a1=0,a2=0,a3=0,a4=0,a5=0,a6=0,a7=0;
            #pragma unroll
            for (int qb = 0; qb < 8; qb++) {
                int q = qb * 32 + lane;
                float av = Wv[jj * H_DIM + q];
                const float* ir = bufB + q * 9;
                a0 += av*ir[0]; a1 += av*ir[1]; a2 += av*ir[2]; a3 += av*ir[3];
                a4 += av*ir[4]; a5 += av*ir[5]; a6 += av*ir[6]; a7 += av*ir[7];
            }
            a0=wred(a0); a1=wred(a1); a2=wred(a2); a3=wred(a3);
            a4=wred(a4); a5=wred(a5); a6=wred(a6); a7=wred(a7);
            if (lane == 0) {
                float* orow = bufA + jj * 9;
                orow[0]=a0; orow[1]=a1; orow[2]=a2; orow[3]=a3;
                orow[4]=a4; orow[5]=a5; orow[6]=a6; orow[7]=a7;
            }
        }
        __syncthreads();
        for (int j = lane; j < H_DIM; j += 32) biask += b2[j] * bufA[j * 9 + warp];
        // Craw = W2 @ P2 -> global
        for (int jj = warp; jj < H_DIM; jj += 8) {
            float a0=0,a1=0,a2=0,a3=0,a4=0,a5=0,a6=0,a7=0;
            #pragma unroll
            for (int qb = 0; qb < 8; qb++) {
                int q = qb * 32 + lane;
                float av = W2[jj * H_DIM + q];
                const float* ir = bufA + q * 9;
                a0 += av*ir[0]; a1 += av*ir[1]; a2 += av*ir[2]; a3 += av*ir[3];
                a4 += av*ir[4]; a5 += av*ir[5]; a6 += av*ir[6]; a7 += av*ir[7];
            }
            a0=wred(a0); a1=wred(a1); a2=wred(a2); a3=wred(a3);
            a4=wred(a4); a5=wred(a5); a6=wred(a6); a7=wred(a7);
            if (lane == 0) {
                float* orow = g_Craw + jj * 8;
                orow[0]=a0; orow[1]=a1; orow[2]=a2; orow[3]=a3;
                orow[4]=a4; orow[5]=a5; orow[6]=a6; orow[7]=a7;
            }
        }
        biask = wred(biask);
        if (lane == 0) g_biaspart[warp] = biask + bp[warp];
    } else {
        // ============ phase 1: gather + cache nc + relu stats ============
        int s1 = (b - 1) * PER1;
        int e1 = s1 + PER1; if (e1 > PAIRS) e1 = PAIRS;
        ulonglong2* ncs2 = (ulonglong2*)s_buf;   // [4][256] dim-pair groups
        const float4* nf4 = (const float4*)nf;

        const ulonglong2* wd = (const ulonglong2*)&w1s[t * 8];
        ulonglong2 w01 = wd[0], w23 = wd[1], w45 = wd[2], w67 = wd[3];
        u64 bdup = b1s[t];
        u64 sum2 = 0ull, sq2 = 0ull;

        for (int base = s1; base < e1; base += 256) {
            int cnt = e1 - base; if (cnt > 256) cnt = 256;
            __syncthreads();
            if (t < cnt) {
                int p  = base + t;
                int e0 = 2 * p;
                int sA = eidx[e0],         sB = eidx[e0 + 1];
                int dA = eidx[E_NUM + e0], dB = eidx[E_NUM + e0 + 1];
                float4 sa0 = nf4[2*sA], sa1 = nf4[2*sA+1];
                float4 da0 = nf4[2*dA], da1 = nf4[2*dA+1];
                float4 sb0 = nf4[2*sB], sb1 = nf4[2*sB+1];
                float4 db0 = nf4[2*dB], db1 = nf4[2*dB+1];
                u64 n0 = pack2(0.5f*(sa0.x+da0.x), 0.5f*(sb0.x+db0.x));
                u64 n1 = pack2(0.5f*(sa0.y+da0.y), 0.5f*(sb0.y+db0.y));
                u64 n2 = pack2(0.5f*(sa0.z+da0.z), 0.5f*(sb0.z+db0.z));
                u64 n3 = pack2(0.5f*(sa0.w+da0.w), 0.5f*(sb0.w+db0.w));
                u64 n4 = pack2(0.5f*(sa1.x+da1.x), 0.5f*(sb1.x+db1.x));
                u64 n5 = pack2(0.5f*(sa1.y+da1.y), 0.5f*(sb1.y+db1.y));
                u64 n6 = pack2(0.5f*(sa1.z+da1.z), 0.5f*(sb1.z+db1.z));
                u64 n7 = pack2(0.5f*(sa1.w+da1.w), 0.5f*(sb1.w+db1.w));
                ncs2[t]       = make_ulonglong2(n0, n1);
                ncs2[256 + t] = make_ulonglong2(n2, n3);
                ncs2[512 + t] = make_ulonglong2(n4, n5);
                ncs2[768 + t] = make_ulonglong2(n6, n7);
                ulonglong2* dst = (ulonglong2*)&g_nc2[(size_t)p * 8];
                dst[0] = make_ulonglong2(n0, n1);
                dst[1] = make_ulonglong2(n2, n3);
                dst[2] = make_ulonglong2(n4, n5);
                dst[3] = make_ulonglong2(n6, n7);
            }
            __syncthreads();
            for (int e2 = 0; e2 < cnt; e2++) {
                ulonglong2 c01 = ncs2[e2];
                ulonglong2 c23 = ncs2[256 + e2];
                ulonglong2 c45 = ncs2[512 + e2];
                ulonglong2 c67 = ncs2[768 + e2];
                u64 h1 = fma2(c01.x, w01.x, bdup);
                h1 = fma2(c01.y, w01.y, h1);
                h1 = fma2(c23.x, w23.x, h1);
                h1 = fma2(c23.y, w23.y, h1);
                u64 h2 = mul2(c45.x, w45.x);
                h2 = fma2(c45.y, w45.y, h2);
                h2 = fma2(c67.x, w67.x, h2);
                h2 = fma2(c67.y, w67.y, h2);
                u64 h = relu2(add2(h1, h2));
                sum2 = add2(sum2, h);
                sq2  = fma2(h, h, sq2);
            }
        }
        float slo, shi, qlo, qhi;
        unpack2(sum2, slo, shi);
        unpack2(sq2, qlo, qhi);
        atomicAdd(&g_sum[t],   slo + shi);
        atomicAdd(&g_sumsq[t], qlo + qhi);
    }

    // ============ grid barrier ============
    __syncthreads();
    if (t == 0) {
        __threadfence();
        if (atomicAdd(&g_arrive, 1) == GRID - 1) {
            g_release = 1;
        } else {
            while (g_release == 0) { }
        }
        __threadfence();
    }
    __syncthreads();

    // ============ finalize BN, dh, ms (per block) ============
    {
        const float invE = 1.f / (float)E_NUM;
        float mu  = g_sum[t] * invE;
        float var = g_sumsq[t] * invE - mu * mu;
        float aj  = gamma[t] * rsqrtf(var + BN_EPS);
        a_s[t] = aj;
        c_s[t] = beta[t] - mu * aj;
    }
    __syncthreads();
    {
        float acc = 0.f;
        for (int j = lane; j < H_DIM; j += 32) acc += c_s[j] * g_Craw[j * 8 + warp];
        acc = wred(acc);
        if (lane == 0) {
            float d = 0.5f * (acc + g_biaspart[warp]);
            dh_s[warp] = pack2(d, d);
        }
    }
    u64* ms = (u64*)s_buf;
    __syncthreads();
    for (int i = t; i < H_DIM * 8; i += 256) {
        float m = 0.5f * a_s[i >> 3] * g_Craw[i];
        ms[i] = pack2(m, m);
    }
    __syncthreads();

    // ============ phase 2: main contraction, 1 pair/thread ============
    int s2 = b * PER2;
    int e2lim = s2 + PER2; if (e2lim > PAIRS) e2lim = PAIRS;
    const float4* ea4 = (const float4*)ea;
    float4* out4 = (float4*)out;

    u64 dh0 = dh_s[0], dh1 = dh_s[1], dh2 = dh_s[2], dh3 = dh_s[3];
    u64 dh4 = dh_s[4], dh5 = dh_s[5], dh6 = dh_s[6], dh7 = dh_s[7];

    for (int base = s2; base < e2lim; base += 256) {
        int p = base + t;
        bool valid = p < e2lim;

        ulonglong2 n01, n23, n45, n67;
        if (valid) {
            const ulonglong2* g = (const ulonglong2*)&g_nc2[(size_t)p * 8];
            n01 = g[0]; n23 = g[1]; n45 = g[2]; n67 = g[3];
        } else {
            n01 = n23 = n45 = n67 = make_ulonglong2(0ull, 0ull);
        }

        u64 a0 = dh0, a1 = dh1, a2 = dh2, a3 = dh3;
        u64 a4 = dh4, a5 = dh5, a6 = dh6, a7 = dh7;

        #pragma unroll 2
        for (int j = 0; j < H_DIM; j++) {
            const ulonglong2* w = (const ulonglong2*)&w1s[j * 8];
            ulonglong2 w01 = w[0], w23 = w[1], w45 = w[2], w67 = w[3];
            u64 h1 = fma2(n01.x, w01.x, b1s[j]);
            h1 = fma2(n01.y, w01.y, h1);
            h1 = fma2(n23.x, w23.x, h1);
            h1 = fma2(n23.y, w23.y, h1);
            u64 h2 = mul2(n45.x, w45.x);
            h2 = fma2(n45.y, w45.y, h2);
            h2 = fma2(n67.x, w67.x, h2);
            h2 = fma2(n67.y, w67.y, h2);
            u64 h = relu2(add2(h1, h2));
            const ulonglong2* m = (const ulonglong2*)&ms[j * 8];
            ulonglong2 m01 = m[0], m23 = m[1], m45 = m[2], m67 = m[3];
            a0 = fma2(h, m01.x, a0); a1 = fma2(h, m01.y, a1);
            a2 = fma2(h, m23.x, a2); a3 = fma2(h, m23.y, a3);
            a4 = fma2(h, m45.x, a4); a5 = fma2(h, m45.y, a5);
            a6 = fma2(h, m67.x, a6); a7 = fma2(h, m67.y, a7);
        }

        if (valid) {
            float4 e0 = ea4[4*p+0], e1 = ea4[4*p+1], e2 = ea4[4*p+2], e3 = ea4[4*p+3];
            float lo, hi; float4 o0, o1, o2, o3;
            unpack2(a0, lo, hi); o0.x = e0.x + lo; o2.x = e2.x + hi;
            unpack2(a1, lo, hi); o0.y = e0.y + lo; o2.y = e2.y + hi;
            unpack2(a2, lo, hi); o0.z = e0.z + lo; o2.z = e2.z + hi;
            unpack2(a3, lo, hi); o0.w = e0.w + lo; o2.w = e2.w + hi;
            unpack2(a4, lo, hi); o1.x = e1.x + lo; o3.x = e3.x + hi;
            unpack2(a5, lo, hi); o1.y = e1.y + lo; o3.y = e3.y + hi;
            unpack2(a6, lo, hi); o1.z = e1.z + lo; o3.z = e3.z + hi;
            unpack2(a7, lo, hi); o1.w = e1.w + lo; o3.w = e3.w + hi;
            out4[4*p+0] = o0; out4[4*p+1] = o1; out4[4*p+2] = o2; out4[4*p+3] = o3;
        }
    }

    // ============ reset (last finisher) ============
    __syncthreads();
    if (t == 0) {
        __threadfence();
        if (atomicAdd(&g_finish, 1) == GRID - 1) {
            g_arrive = 0;
            g_release = 0;
            for (int i = 0; i < H_DIM; i++) { g_sum[i] = 0.f; g_sumsq[i] = 0.f; }
            __threadfence();
            g_finish = 0;
        }
    }
}

// -------- launch --------
extern "C" void kernel_launch(void* const* d_in, const int* in_sizes, int n_in,
                              void* d_out, int out_size) {
    (void)in_sizes; (void)n_in; (void)out_size;
    const float* edge_attr = (const float*)d_in[0];
    const float* nf        = (const float*)d_in[1];
    const int*   eidx      = (const int*)d_in[2];
    // d_in[3..8] = edge-encoder weights: dead code in the reference
    const float* W1    = (const float*)d_in[9];
    const float* b1    = (const float*)d_in[10];
    const float* gamma = (const float*)d_in[11];
    const float* beta  = (const float*)d_in[12];
    const float* W2    = (const float*)d_in[13];
    const float* b2    = (const float*)d_in[14];
    const float* Wv    = (const float*)d_in[15];
    const float* bv    = (const float*)d_in[16];
    const float* Wo    = (const float*)d_in[17];
    const float* bo    = (const float*)d_in[18];
    const float* Wp    = (const float*)d_in[19];
    const float* bp    = (const float*)d_in[20];
    float* out = (float*)d_out;

    fused<<<GRID, 256>>>(edge_attr, nf, eidx, W1, b1, gamma, beta,
                         W2, b2, Wv, bv, Wo, bo, Wp, bp, out);
}

// round 5
// speedup vs baseline: 1.4368x; 1.4368x over previous
#include <cuda_runtime.h>
#include <cstdint>

#define E_NUM   500000
#define H_DIM   256
#define PAIRS   (E_NUM / 2)      // 250000
#define BN_EPS  1e-5f
#define GRID    296              // 148 SMs x 2 co-resident blocks
#define PER1    848              // pairs/block for stats, blocks 1..295
#define TGTOT   75776            // 296*256 threads
#define MAIN3   227328           // 3*TGTOT pairs covered by the 3-pair loop
#define REM     22672            // PAIRS - MAIN3

typedef unsigned long long u64;

// -------- device scratch (static, no allocation) --------
__device__ float g_sum[H_DIM];                     // zero-init
__device__ float g_sumsq[H_DIM];
__device__ __align__(16) u64 g_nc2[PAIRS * 8];     // packed nc pairs, 16 MB
__device__ float g_Craw[H_DIM * 8];                // W2@Wv@Wo@Wp
__device__ float g_biaspart[8];                    // b2@P2 + bv@P1 + bo@Wp + bp
__device__ unsigned g_arrive = 0;
__device__ volatile unsigned g_release = 0;
__device__ unsigned g_finish = 0;

// -------- f32x2 helpers --------
__device__ __forceinline__ u64 pack2(float lo, float hi) {
    u64 r;
    asm("mov.b64 %0, {%1, %2};" : "=l"(r)
        : "r"(__float_as_uint(lo)), "r"(__float_as_uint(hi)));
    return r;
}
__device__ __forceinline__ void unpack2(u64 v, float &lo, float &hi) {
    unsigned int a, b;
    asm("mov.b64 {%0, %1}, %2;" : "=r"(a), "=r"(b) : "l"(v));
    lo = __uint_as_float(a); hi = __uint_as_float(b);
}
__device__ __forceinline__ u64 fma2(u64 a, u64 b, u64 c) {
    u64 d;
    asm("fma.rn.f32x2 %0, %1, %2, %3;" : "=l"(d) : "l"(a), "l"(b), "l"(c));
    return d;
}
__device__ __forceinline__ u64 add2(u64 a, u64 b) {
    u64 d;
    asm("add.rn.f32x2 %0, %1, %2;" : "=l"(d) : "l"(a), "l"(b));
    return d;
}
__device__ __forceinline__ u64 relu2(u64 h) {
    float lo, hi; unpack2(h, lo, hi);
    return pack2(fmaxf(lo, 0.f), fmaxf(hi, 0.f));
}
__device__ __forceinline__ float wred(float v) {
    v += __shfl_down_sync(0xffffffffu, v, 16);
    v += __shfl_down_sync(0xffffffffu, v, 8);
    v += __shfl_down_sync(0xffffffffu, v, 4);
    v += __shfl_down_sync(0xffffffffu, v, 2);
    v += __shfl_down_sync(0xffffffffu, v, 1);
    return v;
}

__global__ void __launch_bounds__(256, 2)
fused(const float* __restrict__ ea, const float* __restrict__ nf,
      const int*   __restrict__ eidx,
      const float* __restrict__ W1, const float* __restrict__ b1,
      const float* __restrict__ gamma, const float* __restrict__ beta,
      const float* __restrict__ W2, const float* __restrict__ b2,
      const float* __restrict__ Wv, const float* __restrict__ bv,
      const float* __restrict__ Wo, const float* __restrict__ bo,
      const float* __restrict__ Wp, const float* __restrict__ bp,
      float* __restrict__ out)
{
    // union: phase1 ncs (u64[2048]) / block0 chain bufs (2x2304 floats) / phase2 ms
    __shared__ __align__(16) unsigned char s_buf[18432];
    __shared__ __align__(16) u64 w1s[H_DIM * 8];   // W1^T duplicated
    __shared__ u64 b1s[H_DIM];
    __shared__ u64 dh_s[8];
    __shared__ float a_s[H_DIM], c_s[H_DIM];

    const int t = threadIdx.x;
    const int b = blockIdx.x;
    const int lane = t & 31, warp = t >> 5;

    // duplicated W1^T / b1 tables
    #pragma unroll
    for (int d = 0; d < 8; d++) {
        float v = W1[d * H_DIM + t];
        w1s[t * 8 + d] = pack2(v, v);
    }
    { float bb = b1[t]; b1s[t] = pack2(bb, bb); }

    if (b == 0) {
        // ============ weight chain (overlaps the stats pass) ============
        float* bufA = (float*)s_buf;      // 256 rows x 9 floats (padded)
        float* bufB = bufA + 2304;
        for (int i = t; i < H_DIM * 8; i += 256)
            bufA[(i >> 3) * 9 + (i & 7)] = Wp[i];
        __syncthreads();
        float biask = 0.f;
        for (int j = lane; j < H_DIM; j += 32) biask += bo[j] * bufA[j * 9 + warp];
        // P1 = Wo @ Wp
        for (int jj = warp; jj < H_DIM; jj += 8) {
            float a0=0,a1=0,a2=0,a3=0,a4=0,a5=0,a6=0,a7=0;
            #pragma unroll
            for (int qb = 0; qb < 8; qb++) {
                int q = qb * 32 + lane;
                float av = Wo[jj * H_DIM + q];
                const float* ir = bufA + q * 9;
                a0 += av*ir[0]; a1 += av*ir[1]; a2 += av*ir[2]; a3 += av*ir[3];
                a4 += av*ir[4]; a5 += av*ir[5]; a6 += av*ir[6]; a7 += av*ir[7];
            }
            a0=wred(a0); a1=wred(a1); a2=wred(a2); a3=wred(a3);
            a4=wred(a4); a5=wred(a5); a6=wred(a6); a7=wred(a7);
            if (lane == 0) {
                float* orow = bufB + jj * 9;
                orow[0]=a0; orow[1]=a1; orow[2]=a2; orow[3]=a3;
                orow[4]=a4; orow[5]=a5; orow[6]=a6; orow[7]=a7;
            }
        }
        __syncthreads();
        for (int j = lane; j < H_DIM; j += 32) biask += bv[j] * bufB[j * 9 + warp];
        // P2 = Wv @ P1
        for (int jj = warp; jj < H_DIM; jj += 8) {
            float a0=0,a1=0,a2=0,a3=0,a4=0,a5=0,a6=0,a7=0;
            #pragma unroll
            for (int qb = 0; qb < 8; qb++) {
                int q = qb * 32 + lane;
                float av = Wv[jj * H_DIM + q];
                const float* ir = bufB + q * 9;
                a0 += av*ir[0]; a1 += av*ir[1]; a2 += av*ir[2]; a3 += av*ir[3];
                a4 += av*ir[4]; a5 += av*ir[5]; a6 += av*ir[6]; a7 += av*ir[7];
            }
            a0=wred(a0); a1=wred(a1); a2=wred(a2); a3=wred(a3);
            a4=wred(a4); a5=wred(a5); a6=wred(a6); a7=wred(a7);
            if (lane == 0) {
                float* orow = bufA + jj * 9;
                orow[0]=a0; orow[1]=a1; orow[2]=a2; orow[3]=a3;
                orow[4]=a4; orow[5]=a5; orow[6]=a6; orow[7]=a7;
            }
        }
        __syncthreads();
        for (int j = lane; j < H_DIM; j += 32) biask += b2[j] * bufA[j * 9 + warp];
        // Craw = W2 @ P2 -> global
        for (int jj = warp; jj < H_DIM; jj += 8) {
            float a0=0,a1=0,a2=0,a3=0,a4=0,a5=0,a6=0,a7=0;
            #pragma unroll
            for (int qb = 0; qb < 8; qb++) {
                int q = qb * 32 + lane;
                float av = W2[jj * H_DIM + q];
                const float* ir = bufA + q * 9;
                a0 += av*ir[0]; a1 += av*ir[1]; a2 += av*ir[2]; a3 += av*ir[3];
                a4 += av*ir[4]; a5 += av*ir[5]; a6 += av*ir[6]; a7 += av*ir[7];
            }
            a0=wred(a0); a1=wred(a1); a2=wred(a2); a3=wred(a3);
            a4=wred(a4); a5=wred(a5); a6=wred(a6); a7=wred(a7);
            if (lane == 0) {
                float* orow = g_Craw + jj * 8;
                orow[0]=a0; orow[1]=a1; orow[2]=a2; orow[3]=a3;
                orow[4]=a4; orow[5]=a5; orow[6]=a6; orow[7]=a7;
            }
        }
        biask = wred(biask);
        if (lane == 0) g_biaspart[warp] = biask + bp[warp];
    } else {
        // ============ phase 1: gather + cache nc + relu stats (R3 verbatim) ==
        int s1 = (b - 1) * PER1;
        int e1 = s1 + PER1; if (e1 > PAIRS) e1 = PAIRS;
        u64* ncs = (u64*)s_buf;
        const float4* nf4 = (const float4*)nf;

        const ulonglong2* wd = (const ulonglong2*)&w1s[t * 8];
        ulonglong2 w01 = wd[0], w23 = wd[1], w45 = wd[2], w67 = wd[3];
        u64 bdup = b1s[t];
        u64 sum2 = 0ull, sq2 = 0ull;

        for (int base = s1; base < e1; base += 256) {
            int cnt = e1 - base; if (cnt > 256) cnt = 256;
            __syncthreads();
            if (t < cnt) {
                int p  = base + t;
                int e0 = 2 * p;
                int sA = eidx[e0],         sB = eidx[e0 + 1];
                int dA = eidx[E_NUM + e0], dB = eidx[E_NUM + e0 + 1];
                float4 sa0 = nf4[2*sA], sa1 = nf4[2*sA+1];
                float4 da0 = nf4[2*dA], da1 = nf4[2*dA+1];
                float4 sb0 = nf4[2*sB], sb1 = nf4[2*sB+1];
                float4 db0 = nf4[2*dB], db1 = nf4[2*dB+1];
                u64 ncp[8];
                ncp[0] = pack2(0.5f*(sa0.x+da0.x), 0.5f*(sb0.x+db0.x));
                ncp[1] = pack2(0.5f*(sa0.y+da0.y), 0.5f*(sb0.y+db0.y));
                ncp[2] = pack2(0.5f*(sa0.z+da0.z), 0.5f*(sb0.z+db0.z));
                ncp[3] = pack2(0.5f*(sa0.w+da0.w), 0.5f*(sb0.w+db0.w));
                ncp[4] = pack2(0.5f*(sa1.x+da1.x), 0.5f*(sb1.x+db1.x));
                ncp[5] = pack2(0.5f*(sa1.y+da1.y), 0.5f*(sb1.y+db1.y));
                ncp[6] = pack2(0.5f*(sa1.z+da1.z), 0.5f*(sb1.z+db1.z));
                ncp[7] = pack2(0.5f*(sa1.w+da1.w), 0.5f*(sb1.w+db1.w));
                #pragma unroll
                for (int d = 0; d < 8; d++) ncs[t * 8 + d] = ncp[d];
                ulonglong2* dst = (ulonglong2*)&g_nc2[(size_t)p * 8];
                dst[0] = make_ulonglong2(ncp[0], ncp[1]);
                dst[1] = make_ulonglong2(ncp[2], ncp[3]);
                dst[2] = make_ulonglong2(ncp[4], ncp[5]);
                dst[3] = make_ulonglong2(ncp[6], ncp[7]);
            }
            __syncthreads();
            for (int e2 = 0; e2 < cnt; e2++) {
                const ulonglong2* c = (const ulonglong2*)&ncs[e2 * 8];
                ulonglong2 c01 = c[0], c23 = c[1], c45 = c[2], c67 = c[3];
                u64 h = bdup;
                h = fma2(c01.x, w01.x, h); h = fma2(c01.y, w01.y, h);
                h = fma2(c23.x, w23.x, h); h = fma2(c23.y, w23.y, h);
                h = fma2(c45.x, w45.x, h); h = fma2(c45.y, w45.y, h);
                h = fma2(c67.x, w67.x, h); h = fma2(c67.y, w67.y, h);
                h = relu2(h);
                sum2 = add2(sum2, h);
                sq2  = fma2(h, h, sq2);
            }
        }
        float slo, shi, qlo, qhi;
        unpack2(sum2, slo, shi);
        unpack2(sq2, qlo, qhi);
        atomicAdd(&g_sum[t],   slo + shi);
        atomicAdd(&g_sumsq[t], qlo + qhi);
    }

    // ============ grid barrier ============
    __syncthreads();
    if (t == 0) {
        __threadfence();
        if (atomicAdd(&g_arrive, 1) == GRID - 1) {
            g_release = 1;
        } else {
            while (g_release == 0) { }
        }
        __threadfence();
    }
    __syncthreads();

    // ============ finalize BN, dh, ms (per block) ============
    {
        const float invE = 1.f / (float)E_NUM;
        float mu  = g_sum[t] * invE;
        float var = g_sumsq[t] * invE - mu * mu;
        float aj  = gamma[t] * rsqrtf(var + BN_EPS);
        a_s[t] = aj;
        c_s[t] = beta[t] - mu * aj;
    }
    __syncthreads();
    {
        float acc = 0.f;
        for (int j = lane; j < H_DIM; j += 32) acc += c_s[j] * g_Craw[j * 8 + warp];
        acc = wred(acc);
        if (lane == 0) {
            float d = 0.5f * (acc + g_biaspart[warp]);
            dh_s[warp] = pack2(d, d);
        }
    }
    u64* ms = (u64*)s_buf;
    __syncthreads();
    for (int i = t; i < H_DIM * 8; i += 256) {
        float m = 0.5f * a_s[i >> 3] * g_Craw[i];
        ms[i] = pack2(m, m);
    }
    __syncthreads();

    // ============ phase 2: 3 pairs/thread, no valid checks ============
    const int tg = b * 256 + t;
    const float4* ea4 = (const float4*)ea;
    float4* out4 = (float4*)out;

    {
        ulonglong2 n[3][4];
        #pragma unroll
        for (int q = 0; q < 3; q++) {
            const ulonglong2* g = (const ulonglong2*)&g_nc2[(size_t)(tg + q * TGTOT) * 8];
            n[q][0] = g[0]; n[q][1] = g[1]; n[q][2] = g[2]; n[q][3] = g[3];
        }
        u64 acc[3][8];
        #pragma unroll
        for (int q = 0; q < 3; q++) {
            #pragma unroll
            for (int k = 0; k < 8; k++) acc[q][k] = dh_s[k];
        }

        #pragma unroll 2
        for (int j = 0; j < H_DIM; j++) {
            const ulonglong2* w = (const ulonglong2*)&w1s[j * 8];
            ulonglong2 w01 = w[0], w23 = w[1], w45 = w[2], w67 = w[3];
            u64 bb = b1s[j];
            const ulonglong2* m = (const ulonglong2*)&ms[j * 8];
            ulonglong2 m01 = m[0], m23 = m[1], m45 = m[2], m67 = m[3];
            #pragma unroll
            for (int q = 0; q < 3; q++) {
                u64 h = fma2(n[q][0].x, w01.x, bb);
                h = fma2(n[q][0].y, w01.y, h);
                h = fma2(n[q][1].x, w23.x, h);
                h = fma2(n[q][1].y, w23.y, h);
                h = fma2(n[q][2].x, w45.x, h);
                h = fma2(n[q][2].y, w45.y, h);
                h = fma2(n[q][3].x, w67.x, h);
                h = fma2(n[q][3].y, w67.y, h);
                h = relu2(h);
                acc[q][0] = fma2(h, m01.x, acc[q][0]); acc[q][1] = fma2(h, m01.y, acc[q][1]);
                acc[q][2] = fma2(h, m23.x, acc[q][2]); acc[q][3] = fma2(h, m23.y, acc[q][3]);
                acc[q][4] = fma2(h, m45.x, acc[q][4]); acc[q][5] = fma2(h, m45.y, acc[q][5]);
                acc[q][6] = fma2(h, m67.x, acc[q][6]); acc[q][7] = fma2(h, m67.y, acc[q][7]);
            }
        }

        #pragma unroll
        for (int q = 0; q < 3; q++) {
            int p = tg + q * TGTOT;
            float4 e0 = ea4[4*p+0], e1 = ea4[4*p+1], e2 = ea4[4*p+2], e3 = ea4[4*p+3];
            float lo, hi; float4 o0, o1, o2, o3;
            unpack2(acc[q][0], lo, hi); o0.x = e0.x + lo; o2.x = e2.x + hi;
            unpack2(acc[q][1], lo, hi); o0.y = e0.y + lo; o2.y = e2.y + hi;
            unpack2(acc[q][2], lo, hi); o0.z = e0.z + lo; o2.z = e2.z + hi;
            unpack2(acc[q][3], lo, hi); o0.w = e0.w + lo; o2.w = e2.w + hi;
            unpack2(acc[q][4], lo, hi); o1.x = e1.x + lo; o3.x = e3.x + hi;
            unpack2(acc[q][5], lo, hi); o1.y = e1.y + lo; o3.y = e3.y + hi;
            unpack2(acc[q][6], lo, hi); o1.z = e1.z + lo; o3.z = e3.z + hi;
            unpack2(acc[q][7], lo, hi); o1.w = e1.w + lo; o3.w = e3.w + hi;
            out4[4*p+0] = o0; out4[4*p+1] = o1; out4[4*p+2] = o2; out4[4*p+3] = o3;
        }
    }

    // remainder: last 22672 pairs, 1 per thread, blocks 0..88 only
    if (tg < REM) {
        int p = tg + MAIN3;
        const ulonglong2* g = (const ulonglong2*)&g_nc2[(size_t)p * 8];
        ulonglong2 n01 = g[0], n23 = g[1], n45 = g[2], n67 = g[3];
        u64 a0 = dh_s[0], a1 = dh_s[1], a2 = dh_s[2], a3 = dh_s[3];
        u64 a4 = dh_s[4], a5 = dh_s[5], a6 = dh_s[6], a7 = dh_s[7];
        #pragma unroll 4
        for (int j = 0; j < H_DIM; j++) {
            const ulonglong2* w = (const ulonglong2*)&w1s[j * 8];
            ulonglong2 w01 = w[0], w23 = w[1], w45 = w[2], w67 = w[3];
            u64 h = fma2(n01.x, w01.x, b1s[j]);
            h = fma2(n01.y, w01.y, h);
            h = fma2(n23.x, w23.x, h);
            h = fma2(n23.y, w23.y, h);
            h = fma2(n45.x, w45.x, h);
            h = fma2(n45.y, w45.y, h);
            h = fma2(n67.x, w67.x, h);
            h = fma2(n67.y, w67.y, h);
            h = relu2(h);
            const ulonglong2* m = (const ulonglong2*)&ms[j * 8];
            ulonglong2 m01 = m[0], m23 = m[1], m45 = m[2], m67 = m[3];
            a0 = fma2(h, m01.x, a0); a1 = fma2(h, m01.y, a1);
            a2 = fma2(h, m23.x, a2); a3 = fma2(h, m23.y, a3);
            a4 = fma2(h, m45.x, a4); a5 = fma2(h, m45.y, a5);
            a6 = fma2(h, m67.x, a6); a7 = fma2(h, m67.y, a7);
        }
        float4 e0 = ea4[4*p+0], e1 = ea4[4*p+1], e2 = ea4[4*p+2], e3 = ea4[4*p+3];
        float lo, hi; float4 o0, o1, o2, o3;
        unpack2(a0, lo, hi); o0.x = e0.x + lo; o2.x = e2.x + hi;
        unpack2(a1, lo, hi); o0.y = e0.y + lo; o2.y = e2.y + hi;
        unpack2(a2, lo, hi); o0.z = e0.z + lo; o2.z = e2.z + hi;
        unpack2(a3, lo, hi); o0.w = e0.w + lo; o2.w = e2.w + hi;
        unpack2(a4, lo, hi); o1.x = e1.x + lo; o3.x = e3.x + hi;
        unpack2(a5, lo, hi); o1.y = e1.y + lo; o3.y = e3.y + hi;
        unpack2(a6, lo, hi); o1.z = e1.z + lo; o3.z = e3.z + hi;
        unpack2(a7, lo, hi); o1.w = e1.w + lo; o3.w = e3.w + hi;
        out4[4*p+0] = o0; out4[4*p+1] = o1; out4[4*p+2] = o2; out4[4*p+3] = o3;
    }

    // ============ reset (last finisher) ============
    __syncthreads();
    if (t == 0) {
        __threadfence();
        if (atomicAdd(&g_finish, 1) == GRID - 1) {
            g_arrive = 0;
            g_release = 0;
            for (int i = 0; i < H_DIM; i++) { g_sum[i] = 0.f; g_sumsq[i] = 0.f; }
            __threadfence();
            g_finish = 0;
        }
    }
}

// -------- launch --------
extern "C" void kernel_launch(void* const* d_in, const int* in_sizes, int n_in,
                              void* d_out, int out_size) {
    (void)in_sizes; (void)n_in; (void)out_size;
    const float* edge_attr = (const float*)d_in[0];
    const float* nf        = (const float*)d_in[1];
    const int*   eidx      = (const int*)d_in[2];
    // d_in[3..8] = edge-encoder weights: dead code in the reference
    const float* W1    = (const float*)d_in[9];
    const float* b1    = (const float*)d_in[10];
    const float* gamma = (const float*)d_in[11];
    const float* beta  = (const float*)d_in[12];
    const float* W2    = (const float*)d_in[13];
    const float* b2    = (const float*)d_in[14];
    const float* Wv    = (const float*)d_in[15];
    const float* bv    = (const float*)d_in[16];
    const float* Wo    = (const float*)d_in[17];
    const float* bo    = (const float*)d_in[18];
    const float* Wp    = (const float*)d_in[19];
    const float* bp    = (const float*)d_in[20];
    float* out = (float*)d_out;

    fused<<<GRID, 256>>>(edge_attr, nf, eidx, W1, b1, gamma, beta,
                         W2, b2, Wv, bv, Wo, bo, Wp, bp, out);
}